// round 2
// baseline (speedup 1.0000x reference)
#include <cuda_runtime.h>
#include <math.h>

#define BB     4
#define LSEQ   1024
#define INDIM  256
#define DM     512
#define NH     8
#define DHD    64
#define FFD    2048
#define NTOK   (BB*LSEQ)   // 4096

// ---------------- scratch (device globals: allocation-free) ----------------
__device__ float g_x   [NTOK*DM];        // running residual stream
__device__ float g_xn  [NTOK*DM];        // layernorm output
__device__ float g_qkv [NTOK*3*DM];      // fused qkv
__device__ float g_ctx [NTOK*DM];        // attention context
__device__ float g_h   [NTOK*FFD];       // FFN hidden
__device__ unsigned char g_rowall[NTOK]; // all(mask[b,i,:])

// ---------------- SGEMM: C[M,N] = A[M,K] @ W[N,K]^T + bias[N] (+epilogue) ----
// EPI: 0 = bias only, 1 = bias + exact GELU, 2 = bias + residual add
template<int EPI>
__global__ __launch_bounds__(256) void sgemm_nt(
    const float* __restrict__ A, const float* __restrict__ W,
    const float* __restrict__ bias, const float* __restrict__ res,
    float* __restrict__ C, int M, int N, int K)
{
    __shared__ float As[16][132];
    __shared__ float Bs[16][132];
    const int tid = threadIdx.x;
    const int tx = tid & 15, ty = tid >> 4;
    const int bm = blockIdx.y * 128, bn = blockIdx.x * 128;
    const int lr = tid >> 2;          // 0..63
    const int lc = (tid & 3) << 2;    // 0,4,8,12
    const float* Ag = A + (size_t)(bm + lr) * K + lc;
    const float* Wg = W + (size_t)(bn + lr) * K + lc;

    float acc[8][8];
    #pragma unroll
    for (int i = 0; i < 8; i++)
        #pragma unroll
        for (int j = 0; j < 8; j++) acc[i][j] = 0.f;

    for (int k0 = 0; k0 < K; k0 += 16) {
        float4 a0 = *(const float4*)(Ag + k0);
        float4 a1 = *(const float4*)(Ag + (size_t)64 * K + k0);
        float4 w0 = *(const float4*)(Wg + k0);
        float4 w1 = *(const float4*)(Wg + (size_t)64 * K + k0);
        As[lc+0][lr]    = a0.x; As[lc+1][lr]    = a0.y; As[lc+2][lr]    = a0.z; As[lc+3][lr]    = a0.w;
        As[lc+0][lr+64] = a1.x; As[lc+1][lr+64] = a1.y; As[lc+2][lr+64] = a1.z; As[lc+3][lr+64] = a1.w;
        Bs[lc+0][lr]    = w0.x; Bs[lc+1][lr]    = w0.y; Bs[lc+2][lr]    = w0.z; Bs[lc+3][lr]    = w0.w;
        Bs[lc+0][lr+64] = w1.x; Bs[lc+1][lr+64] = w1.y; Bs[lc+2][lr+64] = w1.z; Bs[lc+3][lr+64] = w1.w;
        __syncthreads();
        #pragma unroll
        for (int kk = 0; kk < 16; kk++) {
            float ra[8], rb[8];
            *(float4*)&ra[0] = *(const float4*)&As[kk][ty*8];
            *(float4*)&ra[4] = *(const float4*)&As[kk][ty*8+4];
            *(float4*)&rb[0] = *(const float4*)&Bs[kk][tx*8];
            *(float4*)&rb[4] = *(const float4*)&Bs[kk][tx*8+4];
            #pragma unroll
            for (int i = 0; i < 8; i++)
                #pragma unroll
                for (int j = 0; j < 8; j++) acc[i][j] += ra[i]*rb[j];
        }
        __syncthreads();
    }

    #pragma unroll
    for (int i = 0; i < 8; i++) {
        int m = bm + ty*8 + i;
        #pragma unroll
        for (int j = 0; j < 8; j++) {
            int n = bn + tx*8 + j;
            float v = acc[i][j] + bias[n];
            if (EPI == 1) v = 0.5f * v * (1.f + erff(v * 0.70710678118654752f));
            if (EPI == 2) v += res[(size_t)m * N + n];
            C[(size_t)m * N + n] = v;
        }
    }
}

// ---------------- layernorm: one block (128 thr) per row of 512 ----------------
__global__ __launch_bounds__(128) void ln_kernel(
    const float* __restrict__ X, const float* __restrict__ g,
    const float* __restrict__ b, float* __restrict__ Y)
{
    const int row = blockIdx.x;
    const int tid = threadIdx.x;
    float4 v = *(const float4*)(X + (size_t)row*DM + tid*4);
    float s  = v.x + v.y + v.z + v.w;
    float s2 = v.x*v.x + v.y*v.y + v.z*v.z + v.w*v.w;
    #pragma unroll
    for (int off = 16; off >= 1; off >>= 1) {
        s  += __shfl_xor_sync(0xffffffffu, s,  off);
        s2 += __shfl_xor_sync(0xffffffffu, s2, off);
    }
    __shared__ float sh[8];
    if ((tid & 31) == 0) { sh[tid>>5] = s; sh[4 + (tid>>5)] = s2; }
    __syncthreads();
    s  = sh[0] + sh[1] + sh[2] + sh[3];
    s2 = sh[4] + sh[5] + sh[6] + sh[7];
    float mu  = s * (1.f/DM);
    float var = s2 * (1.f/DM) - mu*mu;
    float inv = rsqrtf(var + 1e-5f);
    float4 gg = *(const float4*)(g + tid*4);
    float4 bb = *(const float4*)(b + tid*4);
    float4 y;
    y.x = (v.x - mu)*inv*gg.x + bb.x;
    y.y = (v.y - mu)*inv*gg.y + bb.y;
    y.z = (v.z - mu)*inv*gg.z + bb.z;
    y.w = (v.w - mu)*inv*gg.w + bb.w;
    *(float4*)(Y + (size_t)row*DM + tid*4) = y;
}

// ---------------- row_all: all(mask[b,i,:]) per row (mask is int32 0/1) ------
__global__ __launch_bounds__(128) void rowall_kernel(
    const int* __restrict__ mask, unsigned char* __restrict__ out)
{
    const int row = blockIdx.x;
    const int tid = threadIdx.x;
    const int* m = mask + (size_t)row * LSEQ;
    int mn = 1;
    #pragma unroll
    for (int c = 0; c < LSEQ / 512; c++) {
        int4 v = *(const int4*)(m + c*512 + tid*4);
        mn = min(mn, min(min(v.x, v.y), min(v.z, v.w)));
    }
    #pragma unroll
    for (int off = 16; off >= 1; off >>= 1)
        mn = min(mn, __shfl_xor_sync(0xffffffffu, mn, off));
    __shared__ int sh[4];
    if ((tid & 31) == 0) sh[tid>>5] = mn;
    __syncthreads();
    if (tid == 0) {
        int r = min(min(sh[0], sh[1]), min(sh[2], sh[3]));
        out[row] = (r != 0) ? 1 : 0;
    }
}

// ---------------- flash attention with inline bias ----------------
// grid: (L/64, H, B), 256 threads. Tiles: 64q x 64k, DH=64, fp32.
__global__ __launch_bounds__(256) void attn_kernel(
    const float* __restrict__ qkv,
    const int* __restrict__ mask,
    const float* __restrict__ adj,
    const unsigned char* __restrict__ rowall,
    const float* __restrict__ logscale,
    float* __restrict__ ctx)
{
    __shared__ float Qts[64][64];  // [d][q]
    __shared__ float KP [64][64];  // K^T [d][k], reused as P [q][k]
    __shared__ float Vs [64][64];  // [k][d]
    const int b = blockIdx.z, h = blockIdx.y;
    const int q0 = blockIdx.x * 64;
    const int tid = threadIdx.x;
    const int tx = tid & 15, ty = tid >> 4;
    const float escale = expf(logscale[0]);
    const int lr = tid >> 2;
    const int lc = (tid & 3) << 2;

    // load Q tile, transposed to [d][q]
    {
        const float* qg = qkv + (size_t)(b*LSEQ + q0 + lr)*(3*DM) + h*DHD;
        #pragma unroll
        for (int dd = 0; dd < DHD; dd += 16) {
            float4 v = *(const float4*)(qg + dd + lc);
            Qts[dd+lc+0][lr] = v.x; Qts[dd+lc+1][lr] = v.y;
            Qts[dd+lc+2][lr] = v.z; Qts[dd+lc+3][lr] = v.w;
        }
    }
    const int qr0 = ty * 4;   // query rows owned
    const int cc0 = tx * 4;   // key cols / dh cols owned

    float o[4][4], mi[4], li[4];
    #pragma unroll
    for (int i = 0; i < 4; i++) {
        mi[i] = -1e30f; li[i] = 0.f;
        #pragma unroll
        for (int j = 0; j < 4; j++) o[i][j] = 0.f;
    }
    bool ra[4];
    #pragma unroll
    for (int i = 0; i < 4; i++) ra[i] = rowall[b*LSEQ + q0 + qr0 + i] != 0;

    for (int k0 = 0; k0 < LSEQ; k0 += 64) {
        // load K (transposed) and V tiles
        const float* kg = qkv + (size_t)(b*LSEQ + k0 + lr)*(3*DM) + DM + h*DHD;
        const float* vg = kg + DM;
        #pragma unroll
        for (int dd = 0; dd < DHD; dd += 16) {
            float4 kv = *(const float4*)(kg + dd + lc);
            KP[dd+lc+0][lr] = kv.x; KP[dd+lc+1][lr] = kv.y;
            KP[dd+lc+2][lr] = kv.z; KP[dd+lc+3][lr] = kv.w;
            float4 vv = *(const float4*)(vg + dd + lc);
            *(float4*)&Vs[lr][dd+lc] = vv;
        }
        __syncthreads();

        // S = Q @ K^T
        float s[4][4];
        #pragma unroll
        for (int i = 0; i < 4; i++)
            #pragma unroll
            for (int j = 0; j < 4; j++) s[i][j] = 0.f;
        #pragma unroll
        for (int d = 0; d < DHD; d++) {
            float4 rq = *(const float4*)&Qts[d][qr0];
            float4 rk = *(const float4*)&KP[d][cc0];
            float q_[4] = {rq.x, rq.y, rq.z, rq.w};
            float k_[4] = {rk.x, rk.y, rk.z, rk.w};
            #pragma unroll
            for (int i = 0; i < 4; i++)
                #pragma unroll
                for (int j = 0; j < 4; j++) s[i][j] += q_[i]*k_[j];
        }

        // inline bias + online softmax (row = 16 lanes sharing ty)
        #pragma unroll
        for (int i = 0; i < 4; i++) {
            const int q = q0 + qr0 + i;
            const size_t rowoff = ((size_t)b*LSEQ + q)*LSEQ + k0 + cc0;
            const int4 mi4 = *(const int4*)(mask + rowoff);
            const float4 ad4 = *(const float4*)(adj + rowoff);
            int   mm_[4] = {mi4.x, mi4.y, mi4.z, mi4.w};
            float ad_[4] = {ad4.x, ad4.y, ad4.z, ad4.w};
            float rowmax = -1e30f;
            #pragma unroll
            for (int j = 0; j < 4; j++) {
                int kk = k0 + cc0 + j;
                float ad = fminf(fmaxf(ad_[j], 0.f), 1.f);
                bool eff = (mm_[j] != 0) && !((kk == q) && ra[i]);
                float val = s[i][j]*0.125f + (eff ? -10000.f : 0.f) + escale*ad;
                s[i][j] = val;
                rowmax = fmaxf(rowmax, val);
            }
            #pragma unroll
            for (int off = 8; off >= 1; off >>= 1)
                rowmax = fmaxf(rowmax, __shfl_xor_sync(0xffffffffu, rowmax, off));
            float mnew = fmaxf(mi[i], rowmax);
            float corr = expf(mi[i] - mnew);
            float psum = 0.f;
            #pragma unroll
            for (int j = 0; j < 4; j++) {
                float p = expf(s[i][j] - mnew);
                s[i][j] = p; psum += p;
            }
            #pragma unroll
            for (int off = 8; off >= 1; off >>= 1)
                psum += __shfl_xor_sync(0xffffffffu, psum, off);
            li[i] = li[i]*corr + psum;
            #pragma unroll
            for (int j = 0; j < 4; j++) o[i][j] *= corr;
            mi[i] = mnew;
        }
        __syncthreads();     // everyone done reading K^T

        // stash P into KP as [q][k]
        #pragma unroll
        for (int i = 0; i < 4; i++)
            #pragma unroll
            for (int j = 0; j < 4; j++) KP[qr0+i][cc0+j] = s[i][j];
        __syncthreads();

        // O += P @ V
        #pragma unroll
        for (int k = 0; k < 64; k++) {
            float4 rv = *(const float4*)&Vs[k][cc0];
            float v_[4] = {rv.x, rv.y, rv.z, rv.w};
            float p0 = KP[qr0+0][k], p1 = KP[qr0+1][k];
            float p2 = KP[qr0+2][k], p3 = KP[qr0+3][k];
            #pragma unroll
            for (int j = 0; j < 4; j++) {
                o[0][j] += p0*v_[j]; o[1][j] += p1*v_[j];
                o[2][j] += p2*v_[j]; o[3][j] += p3*v_[j];
            }
        }
        __syncthreads();     // before next tile overwrites KP/Vs
    }

    // normalize + write ctx in [B, L, H*DH] layout
    #pragma unroll
    for (int i = 0; i < 4; i++) {
        float inv = 1.f / li[i];
        #pragma unroll
        for (int j = 0; j < 4; j++) {
            ctx[(size_t)(b*LSEQ + q0 + qr0 + i)*DM + h*DHD + cc0 + j] = o[i][j]*inv;
        }
    }
}

// ---------------- launch ----------------
extern "C" void kernel_launch(void* const* d_in, const int* in_sizes, int n_in,
                              void* d_out, int out_size)
{
    (void)in_sizes; (void)n_in; (void)out_size;
    const float*         x      = (const float*)d_in[0];
    const int*           amask  = (const int*)d_in[1];
    const float*         adj    = (const float*)d_in[2];
    const float*         Wf     = (const float*)d_in[3];
    const float*         bf     = (const float*)d_in[4];
    const float*         Wqkv   = (const float*)d_in[5];
    const float*         bqkv   = (const float*)d_in[6];
    const float*         Wo     = (const float*)d_in[7];
    const float*         bo     = (const float*)d_in[8];
    const float*         ln1g   = (const float*)d_in[9];
    const float*         ln1b   = (const float*)d_in[10];
    const float*         ln2g   = (const float*)d_in[11];
    const float*         ln2b   = (const float*)d_in[12];
    const float*         W1     = (const float*)d_in[13];
    const float*         b1     = (const float*)d_in[14];
    const float*         W2     = (const float*)d_in[15];
    const float*         b2     = (const float*)d_in[16];
    const float*         lscale = (const float*)d_in[17];
    float* out = (float*)d_out;

    float *gx, *gxn, *gqkv, *gctx, *gh;
    unsigned char* grow;
    cudaGetSymbolAddress((void**)&gx,   g_x);
    cudaGetSymbolAddress((void**)&gxn,  g_xn);
    cudaGetSymbolAddress((void**)&gqkv, g_qkv);
    cudaGetSymbolAddress((void**)&gctx, g_ctx);
    cudaGetSymbolAddress((void**)&gh,   g_h);
    cudaGetSymbolAddress((void**)&grow, g_rowall);

    // 1. fuse projection: g_x = x @ Wf^T + bf
    sgemm_nt<0><<<dim3(DM/128, NTOK/128), 256>>>(x, Wf, bf, nullptr, gx, NTOK, DM, INDIM);
    // 2. row_all over attention_mask
    rowall_kernel<<<NTOK, 128>>>(amask, grow);
    // 3. LN1
    ln_kernel<<<NTOK, 128>>>(gx, ln1g, ln1b, gxn);
    // 4. qkv = xn @ Wqkv^T + b
    sgemm_nt<0><<<dim3((3*DM)/128, NTOK/128), 256>>>(gxn, Wqkv, bqkv, nullptr, gqkv, NTOK, 3*DM, DM);
    // 5. flash attention with inline bias
    attn_kernel<<<dim3(LSEQ/64, NH, BB), 256>>>(gqkv, amask, adj, grow, lscale, gctx);
    // 6. out proj + residual: g_x = g_x + ctx @ Wo^T + bo
    sgemm_nt<2><<<dim3(DM/128, NTOK/128), 256>>>(gctx, Wo, bo, gx, gx, NTOK, DM, DM);
    // 7. LN2
    ln_kernel<<<NTOK, 128>>>(gx, ln2g, ln2b, gxn);
    // 8. FFN up + exact GELU
    sgemm_nt<1><<<dim3(FFD/128, NTOK/128), 256>>>(gxn, W1, b1, nullptr, gh, NTOK, FFD, DM);
    // 9. FFN down + residual -> output
    sgemm_nt<2><<<dim3(DM/128, NTOK/128), 256>>>(gh, W2, b2, gx, out, NTOK, DM, FFD);
}

// round 4
// speedup vs baseline: 1.5769x; 1.5769x over previous
#include <cuda_runtime.h>
#include <math.h>
#include <stdint.h>

#define BB     4
#define LSEQ   1024
#define INDIM  256
#define DM     512
#define NH     8
#define DHD    64
#define FFD    2048
#define NTOK   (BB*LSEQ)   // 4096

// ---------------- scratch (device globals: allocation-free) ----------------
__device__ float g_x   [NTOK*DM];
__device__ float g_xn  [NTOK*DM];
__device__ float g_qkv [NTOK*3*DM];
__device__ float g_ctx [NTOK*DM];
__device__ float g_h   [NTOK*FFD];
__device__ unsigned char g_rowall[NTOK];

__device__ __forceinline__ uint32_t tf32r(float x) {
    uint32_t r; asm("cvt.rna.tf32.f32 %0, %1;" : "=r"(r) : "f"(x)); return r;
}
__device__ __forceinline__ void mma_tf32(float* c, const uint32_t* a, const uint32_t* b) {
    asm volatile(
        "mma.sync.aligned.m16n8k8.row.col.f32.tf32.tf32.f32 "
        "{%0,%1,%2,%3}, {%4,%5,%6,%7}, {%8,%9}, {%0,%1,%2,%3};"
        : "+f"(c[0]), "+f"(c[1]), "+f"(c[2]), "+f"(c[3])
        : "r"(a[0]), "r"(a[1]), "r"(a[2]), "r"(a[3]), "r"(b[0]), "r"(b[1]));
}

// ================= tf32 mma.sync GEMM =================
// C[M,N] = A[M,K] @ W[N,K]^T + bias[N]  (EPI: 0=bias, 1=+exact GELU, 2=+residual)
// BM=BN=128, BK=32; 8 warps in 4(m) x 2(n) grid; warp tile 32m x 64n.
template<int EPI>
__global__ __launch_bounds__(256, 2) void mma_gemm(
    const float* __restrict__ A, const float* __restrict__ W,
    const float* __restrict__ bias, const float* __restrict__ res,
    float* __restrict__ C, int M, int N, int K)
{
    __shared__ uint32_t As[32][132];   // [k][m], tf32 bits
    __shared__ uint32_t Bs[32][132];   // [k][n]
    const int tid = threadIdx.x;
    const int bm = blockIdx.y * 128, bn = blockIdx.x * 128;
    const int lane = tid & 31, warp = tid >> 5;
    const int wm = warp & 3, wn = warp >> 2;
    const int m_base = wm * 32, n_base = wn * 64;
    const int lg = lane >> 2, lt = lane & 3;   // group id, thread-in-group

    float acc[2][8][4];
    #pragma unroll
    for (int mt = 0; mt < 2; mt++)
        #pragma unroll
        for (int nt = 0; nt < 8; nt++)
            #pragma unroll
            for (int c = 0; c < 4; c++) acc[mt][nt][c] = 0.f;

    // global load map: 4 float4 per thread per tile (128 rows x 32 k)
    int am[4], akc[4];
    const float4* Ag[4];
    const float4* Bg[4];
    #pragma unroll
    for (int i = 0; i < 4; i++) {
        int f = i * 256 + tid;
        am[i] = f >> 3; akc[i] = f & 7;
        Ag[i] = (const float4*)(A + (size_t)(bm + am[i]) * K) + akc[i];
        Bg[i] = (const float4*)(W + (size_t)(bn + am[i]) * K) + akc[i];
    }

    const int nc = K / 32;
    for (int c = 0; c < nc; c++) {
        #pragma unroll
        for (int i = 0; i < 4; i++) {
            float4 va = Ag[i][c * 8];
            float4 vb = Bg[i][c * 8];
            int kk = akc[i] * 4, m = am[i];
            As[kk+0][m] = tf32r(va.x); As[kk+1][m] = tf32r(va.y);
            As[kk+2][m] = tf32r(va.z); As[kk+3][m] = tf32r(va.w);
            Bs[kk+0][m] = tf32r(vb.x); Bs[kk+1][m] = tf32r(vb.y);
            Bs[kk+2][m] = tf32r(vb.z); Bs[kk+3][m] = tf32r(vb.w);
        }
        __syncthreads();
        #pragma unroll
        for (int ks = 0; ks < 4; ks++) {
            const int k = ks * 8;
            uint32_t a[2][4], b[8][2];
            #pragma unroll
            for (int mt = 0; mt < 2; mt++) {
                int mr = m_base + mt * 16 + lg;
                a[mt][0] = As[k + lt    ][mr];
                a[mt][1] = As[k + lt    ][mr + 8];
                a[mt][2] = As[k + lt + 4][mr];
                a[mt][3] = As[k + lt + 4][mr + 8];
            }
            #pragma unroll
            for (int nt = 0; nt < 8; nt++) {
                int nr = n_base + nt * 8 + lg;
                b[nt][0] = Bs[k + lt    ][nr];
                b[nt][1] = Bs[k + lt + 4][nr];
            }
            #pragma unroll
            for (int mt = 0; mt < 2; mt++)
                #pragma unroll
                for (int nt = 0; nt < 8; nt++)
                    mma_tf32(acc[mt][nt], a[mt], b[nt]);
        }
        __syncthreads();
    }

    // epilogue: c0,c1 = (row, col), (row, col+1); c2,c3 = row+8
    #pragma unroll
    for (int mt = 0; mt < 2; mt++) {
        #pragma unroll
        for (int nt = 0; nt < 8; nt++) {
            const int row = bm + m_base + mt * 16 + lg;
            const int col = bn + n_base + nt * 8 + lt * 2;
            #pragma unroll
            for (int half = 0; half < 2; half++) {
                const int r = row + half * 8;
                float v0 = acc[mt][nt][half*2+0] + bias[col];
                float v1 = acc[mt][nt][half*2+1] + bias[col+1];
                if (EPI == 1) {
                    v0 = 0.5f * v0 * (1.f + erff(v0 * 0.70710678118654752f));
                    v1 = 0.5f * v1 * (1.f + erff(v1 * 0.70710678118654752f));
                }
                if (EPI == 2) {
                    float2 rr = *(const float2*)(res + (size_t)r * N + col);
                    v0 += rr.x; v1 += rr.y;
                }
                *(float2*)(C + (size_t)r * N + col) = make_float2(v0, v1);
            }
        }
    }
}

// ---------------- layernorm ----------------
__global__ __launch_bounds__(128) void ln_kernel(
    const float* __restrict__ X, const float* __restrict__ g,
    const float* __restrict__ b, float* __restrict__ Y)
{
    const int row = blockIdx.x;
    const int tid = threadIdx.x;
    float4 v = *(const float4*)(X + (size_t)row*DM + tid*4);
    float s  = v.x + v.y + v.z + v.w;
    float s2 = v.x*v.x + v.y*v.y + v.z*v.z + v.w*v.w;
    #pragma unroll
    for (int off = 16; off >= 1; off >>= 1) {
        s  += __shfl_xor_sync(0xffffffffu, s,  off);
        s2 += __shfl_xor_sync(0xffffffffu, s2, off);
    }
    __shared__ float sh[8];
    if ((tid & 31) == 0) { sh[tid>>5] = s; sh[4 + (tid>>5)] = s2; }
    __syncthreads();
    s  = sh[0] + sh[1] + sh[2] + sh[3];
    s2 = sh[4] + sh[5] + sh[6] + sh[7];
    float mu  = s * (1.f/DM);
    float var = s2 * (1.f/DM) - mu*mu;
    float inv = rsqrtf(var + 1e-5f);
    float4 gg = *(const float4*)(g + tid*4);
    float4 bb = *(const float4*)(b + tid*4);
    float4 y;
    y.x = (v.x - mu)*inv*gg.x + bb.x;
    y.y = (v.y - mu)*inv*gg.y + bb.y;
    y.z = (v.z - mu)*inv*gg.z + bb.z;
    y.w = (v.w - mu)*inv*gg.w + bb.w;
    *(float4*)(Y + (size_t)row*DM + tid*4) = y;
}

// ---------------- row_all (mask int32 0/1) ----------------
__global__ __launch_bounds__(128) void rowall_kernel(
    const int* __restrict__ mask, unsigned char* __restrict__ out)
{
    const int row = blockIdx.x;
    const int tid = threadIdx.x;
    const int* m = mask + (size_t)row * LSEQ;
    int mn = 1;
    #pragma unroll
    for (int c = 0; c < LSEQ / 512; c++) {
        int4 v = *(const int4*)(m + c*512 + tid*4);
        mn = min(mn, min(min(v.x, v.y), min(v.z, v.w)));
    }
    #pragma unroll
    for (int off = 16; off >= 1; off >>= 1)
        mn = min(mn, __shfl_xor_sync(0xffffffffu, mn, off));
    __shared__ int sh[4];
    if ((tid & 31) == 0) sh[tid>>5] = mn;
    __syncthreads();
    if (tid == 0) {
        int r = min(min(sh[0], sh[1]), min(sh[2], sh[3]));
        out[row] = (r != 0) ? 1 : 0;
    }
}

// ---------------- flash attention with inline bias (fp32 SIMT) ----------------
__global__ __launch_bounds__(256) void attn_kernel(
    const float* __restrict__ qkv,
    const int* __restrict__ mask,
    const float* __restrict__ adj,
    const unsigned char* __restrict__ rowall,
    const float* __restrict__ logscale,
    float* __restrict__ ctx)
{
    __shared__ float Qts[64][64];
    __shared__ float KP [64][64];
    __shared__ float Vs [64][64];
    const int b = blockIdx.z, h = blockIdx.y;
    const int q0 = blockIdx.x * 64;
    const int tid = threadIdx.x;
    const int tx = tid & 15, ty = tid >> 4;
    const float escale = expf(logscale[0]);
    const int lr = tid >> 2;
    const int lc = (tid & 3) << 2;

    {
        const float* qg = qkv + (size_t)(b*LSEQ + q0 + lr)*(3*DM) + h*DHD;
        #pragma unroll
        for (int dd = 0; dd < DHD; dd += 16) {
            float4 v = *(const float4*)(qg + dd + lc);
            Qts[dd+lc+0][lr] = v.x; Qts[dd+lc+1][lr] = v.y;
            Qts[dd+lc+2][lr] = v.z; Qts[dd+lc+3][lr] = v.w;
        }
    }
    const int qr0 = ty * 4;
    const int cc0 = tx * 4;

    float o[4][4], mi[4], li[4];
    #pragma unroll
    for (int i = 0; i < 4; i++) {
        mi[i] = -1e30f; li[i] = 0.f;
        #pragma unroll
        for (int j = 0; j < 4; j++) o[i][j] = 0.f;
    }
    bool ra[4];
    #pragma unroll
    for (int i = 0; i < 4; i++) ra[i] = rowall[b*LSEQ + q0 + qr0 + i] != 0;

    for (int k0 = 0; k0 < LSEQ; k0 += 64) {
        const float* kg = qkv + (size_t)(b*LSEQ + k0 + lr)*(3*DM) + DM + h*DHD;
        const float* vg = kg + DM;
        #pragma unroll
        for (int dd = 0; dd < DHD; dd += 16) {
            float4 kv = *(const float4*)(kg + dd + lc);
            KP[dd+lc+0][lr] = kv.x; KP[dd+lc+1][lr] = kv.y;
            KP[dd+lc+2][lr] = kv.z; KP[dd+lc+3][lr] = kv.w;
            float4 vv = *(const float4*)(vg + dd + lc);
            *(float4*)&Vs[lr][dd+lc] = vv;
        }
        __syncthreads();

        float s[4][4];
        #pragma unroll
        for (int i = 0; i < 4; i++)
            #pragma unroll
            for (int j = 0; j < 4; j++) s[i][j] = 0.f;
        #pragma unroll
        for (int d = 0; d < DHD; d++) {
            float4 rq = *(const float4*)&Qts[d][qr0];
            float4 rk = *(const float4*)&KP[d][cc0];
            float q_[4] = {rq.x, rq.y, rq.z, rq.w};
            float k_[4] = {rk.x, rk.y, rk.z, rk.w};
            #pragma unroll
            for (int i = 0; i < 4; i++)
                #pragma unroll
                for (int j = 0; j < 4; j++) s[i][j] += q_[i]*k_[j];
        }

        #pragma unroll
        for (int i = 0; i < 4; i++) {
            const int q = q0 + qr0 + i;
            const size_t rowoff = ((size_t)b*LSEQ + q)*LSEQ + k0 + cc0;
            const int4 mi4 = *(const int4*)(mask + rowoff);
            const float4 ad4 = *(const float4*)(adj + rowoff);
            int   mm_[4] = {mi4.x, mi4.y, mi4.z, mi4.w};
            float ad_[4] = {ad4.x, ad4.y, ad4.z, ad4.w};
            float rowmax = -1e30f;
            #pragma unroll
            for (int j = 0; j < 4; j++) {
                int kk = k0 + cc0 + j;
                float ad = fminf(fmaxf(ad_[j], 0.f), 1.f);
                bool eff = (mm_[j] != 0) && !((kk == q) && ra[i]);
                float val = s[i][j]*0.125f + (eff ? -10000.f : 0.f) + escale*ad;
                s[i][j] = val;
                rowmax = fmaxf(rowmax, val);
            }
            #pragma unroll
            for (int off = 8; off >= 1; off >>= 1)
                rowmax = fmaxf(rowmax, __shfl_xor_sync(0xffffffffu, rowmax, off));
            float mnew = fmaxf(mi[i], rowmax);
            float corr = expf(mi[i] - mnew);
            float psum = 0.f;
            #pragma unroll
            for (int j = 0; j < 4; j++) {
                float p = expf(s[i][j] - mnew);
                s[i][j] = p; psum += p;
            }
            #pragma unroll
            for (int off = 8; off >= 1; off >>= 1)
                psum += __shfl_xor_sync(0xffffffffu, psum, off);
            li[i] = li[i]*corr + psum;
            #pragma unroll
            for (int j = 0; j < 4; j++) o[i][j] *= corr;
            mi[i] = mnew;
        }
        __syncthreads();

        #pragma unroll
        for (int i = 0; i < 4; i++)
            #pragma unroll
            for (int j = 0; j < 4; j++) KP[qr0+i][cc0+j] = s[i][j];
        __syncthreads();

        #pragma unroll
        for (int k = 0; k < 64; k++) {
            float4 rv = *(const float4*)&Vs[k][cc0];
            float v_[4] = {rv.x, rv.y, rv.z, rv.w};
            float p0 = KP[qr0+0][k], p1 = KP[qr0+1][k];
            float p2 = KP[qr0+2][k], p3 = KP[qr0+3][k];
            #pragma unroll
            for (int j = 0; j < 4; j++) {
                o[0][j] += p0*v_[j]; o[1][j] += p1*v_[j];
                o[2][j] += p2*v_[j]; o[3][j] += p3*v_[j];
            }
        }
        __syncthreads();
    }

    #pragma unroll
    for (int i = 0; i < 4; i++) {
        float inv = 1.f / li[i];
        #pragma unroll
        for (int j = 0; j < 4; j++) {
            ctx[(size_t)(b*LSEQ + q0 + qr0 + i)*DM + h*DHD + cc0 + j] = o[i][j]*inv;
        }
    }
}

// ---------------- launch ----------------
extern "C" void kernel_launch(void* const* d_in, const int* in_sizes, int n_in,
                              void* d_out, int out_size)
{
    (void)in_sizes; (void)n_in; (void)out_size;
    const float* x      = (const float*)d_in[0];
    const int*   amask  = (const int*)d_in[1];
    const float* adj    = (const float*)d_in[2];
    const float* Wf     = (const float*)d_in[3];
    const float* bf     = (const float*)d_in[4];
    const float* Wqkv   = (const float*)d_in[5];
    const float* bqkv   = (const float*)d_in[6];
    const float* Wo     = (const float*)d_in[7];
    const float* bo     = (const float*)d_in[8];
    const float* ln1g   = (const float*)d_in[9];
    const float* ln1b   = (const float*)d_in[10];
    const float* ln2g   = (const float*)d_in[11];
    const float* ln2b   = (const float*)d_in[12];
    const float* W1     = (const float*)d_in[13];
    const float* b1     = (const float*)d_in[14];
    const float* W2     = (const float*)d_in[15];
    const float* b2     = (const float*)d_in[16];
    const float* lscale = (const float*)d_in[17];
    float* out = (float*)d_out;

    float *gx, *gxn, *gqkv, *gctx, *gh;
    unsigned char* grow;
    cudaGetSymbolAddress((void**)&gx,   g_x);
    cudaGetSymbolAddress((void**)&gxn,  g_xn);
    cudaGetSymbolAddress((void**)&gqkv, g_qkv);
    cudaGetSymbolAddress((void**)&gctx, g_ctx);
    cudaGetSymbolAddress((void**)&gh,   g_h);
    cudaGetSymbolAddress((void**)&grow, g_rowall);

    // 1. fuse projection: g_x = x @ Wf^T + bf
    mma_gemm<0><<<dim3(DM/128, NTOK/128), 256>>>(x, Wf, bf, nullptr, gx, NTOK, DM, INDIM);
    // 2. row_all
    rowall_kernel<<<NTOK, 128>>>(amask, grow);
    // 3. LN1
    ln_kernel<<<NTOK, 128>>>(gx, ln1g, ln1b, gxn);
    // 4. qkv
    mma_gemm<0><<<dim3((3*DM)/128, NTOK/128), 256>>>(gxn, Wqkv, bqkv, nullptr, gqkv, NTOK, 3*DM, DM);
    // 5. attention
    attn_kernel<<<dim3(LSEQ/64, NH, BB), 256>>>(gqkv, amask, adj, grow, lscale, gctx);
    // 6. out proj + residual
    mma_gemm<2><<<dim3(DM/128, NTOK/128), 256>>>(gctx, Wo, bo, gx, gx, NTOK, DM, DM);
    // 7. LN2
    ln_kernel<<<NTOK, 128>>>(gx, ln2g, ln2b, gxn);
    // 8. FFN up + GELU
    mma_gemm<1><<<dim3(FFD/128, NTOK/128), 256>>>(gxn, W1, b1, nullptr, gh, NTOK, FFD, DM);
    // 9. FFN down + residual -> out
    mma_gemm<2><<<dim3(DM/128, NTOK/128), 256>>>(gh, W2, b2, gx, out, NTOK, DM, FFD);
}